// round 3
// baseline (speedup 1.0000x reference)
#include <cuda_runtime.h>
#include <cstdint>

// ---------------------------------------------------------------------------
// CrossWarpingModule: B=2, C=64, H=W=256 -> 4 parity sub-images of 128x128,
// 8-head axial attention (per-head channel dim = 1), flow, bilinear warp.
//
//   K1  k_qkv       : 1x1 convs on packed fma.rn.f32x2 -> Q, K2(=K*log2e), V
//   K1T k_transpose : transposed copies for the vertical axial pass
//   K2  k_attn      : axial softmax -> flow. Exp split across MUFU.EX2 and a
//                     packed FFMA2 magic-round+deg3 polynomial (pipe-balanced).
//   K3  k_warp      : bilinear border grid-sample + parity re-interleave,
//                     channel-split 4x, batched gathers for MLP.
// ---------------------------------------------------------------------------

#define PLANE 16384  // 128*128
typedef unsigned long long u64;
typedef unsigned int u32;

__device__ float g_Q  [8][8][PLANE];
__device__ float g_K2 [8][8][PLANE];
__device__ float g_V  [8][8][PLANE];
__device__ float g_QT [8][8][PLANE];
__device__ float g_K2T[8][8][PLANE];
__device__ float g_VT [8][8][PLANE];
__device__ float g_flow[2][8][PLANE];   // dir0 = horizontal, dir1 = vertical

// ------------------------- packed f32x2 helpers ----------------------------
__device__ __forceinline__ u64 pk2f(float lo, float hi) {
    u64 r; asm("mov.b64 %0,{%1,%2};" : "=l"(r) : "f"(lo), "f"(hi)); return r;
}
__device__ __forceinline__ void upk2f(u64 v, float& lo, float& hi) {
    asm("mov.b64 {%0,%1},%2;" : "=f"(lo), "=f"(hi) : "l"(v));
}
__device__ __forceinline__ u64 pk2u(u32 lo, u32 hi) {
    u64 r; asm("mov.b64 %0,{%1,%2};" : "=l"(r) : "r"(lo), "r"(hi)); return r;
}
__device__ __forceinline__ void upk2u(u64 v, u32& lo, u32& hi) {
    asm("mov.b64 {%0,%1},%2;" : "=r"(lo), "=r"(hi) : "l"(v));
}
__device__ __forceinline__ u64 fma2(u64 a, u64 b, u64 c) {
    u64 d; asm("fma.rn.f32x2 %0,%1,%2,%3;" : "=l"(d) : "l"(a), "l"(b), "l"(c)); return d;
}
__device__ __forceinline__ u64 add2(u64 a, u64 b) {
    u64 d; asm("add.rn.f32x2 %0,%1,%2;" : "=l"(d) : "l"(a), "l"(b)); return d;
}
__device__ __forceinline__ u64 mul2(u64 a, u64 b) {
    u64 d; asm("mul.rn.f32x2 %0,%1,%2;" : "=l"(d) : "l"(a), "l"(b)); return d;
}
__device__ __forceinline__ float ex2a(float x) {
    float e; asm("ex2.approx.f32 %0,%1;" : "=f"(e) : "f"(x)); return e;
}

// ---------------------------------------------------------------------------
// K1: QKV projections, packed. One thread handles 4 consecutive original-x
// pixels as two f32x2 lanes: (x0,x1) and (x2,x3). Weights pre-splatted to u64
// in smem so the whole reduction is fma.rn.f32x2.
// ---------------------------------------------------------------------------
__global__ __launch_bounds__(256) void k_qkv(
    const float* __restrict__ cur, const float* __restrict__ ref,
    const float* __restrict__ Wq, const float* __restrict__ Wk,
    const float* __restrict__ Wv)
{
    __shared__ u64 sW[3][512];
    int t = threadIdx.x;
    for (int i = t; i < 512; i += 256) {
        float wq = Wq[i];
        float wk = Wk[i] * 1.4426950408889634f;  // fold log2(e) into K
        float wv = Wv[i];
        sW[0][i] = pk2f(wq, wq);
        sW[1][i] = pk2f(wk, wk);
        sW[2][i] = pk2f(wv, wv);
    }
    __syncthreads();

    int idx = blockIdx.x * 256 + t;      // 32768 = 2(b) * 256(y) * 64(xq)
    int b   = idx >> 14;
    int rem = idx & 16383;
    int y   = rem >> 6;
    int xq  = rem & 63;
    int h2  = y >> 1, dyp = y & 1;

    u64 qa01[8], qa23[8], ka01[8], ka23[8], va01[8], va23[8];
#pragma unroll
    for (int h = 0; h < 8; ++h) {
        qa01[h] = qa23[h] = 0ull;
        ka01[h] = ka23[h] = 0ull;
        va01[h] = va23[h] = 0ull;
    }

    const float* curp = cur + ((size_t)b * 64) * 65536 + y * 256 + xq * 4;
    const float* refp = ref + ((size_t)b * 64) * 65536 + y * 256 + xq * 4;

#pragma unroll 4
    for (int c = 0; c < 64; ++c) {
        float4 cv = *(const float4*)(curp + (size_t)c * 65536);
        float4 rv = *(const float4*)(refp + (size_t)c * 65536);
        u64 c01 = pk2f(cv.x, cv.y), c23 = pk2f(cv.z, cv.w);
        u64 r01 = pk2f(rv.x, rv.y), r23 = pk2f(rv.z, rv.w);
#pragma unroll
        for (int h = 0; h < 8; ++h) {
            u64 wq = sW[0][h * 64 + c];
            u64 wk = sW[1][h * 64 + c];
            u64 wv = sW[2][h * 64 + c];
            qa01[h] = fma2(wq, c01, qa01[h]);
            qa23[h] = fma2(wq, c23, qa23[h]);
            ka01[h] = fma2(wk, r01, ka01[h]);
            ka23[h] = fma2(wk, r23, ka23[h]);
            va01[h] = fma2(wv, r01, va01[h]);
            va23[h] = fma2(wv, r23, va23[h]);
        }
    }

    // parity sub mapping: (dy,dx) -> s : (0,0)->0 (1,1)->1 (0,1)->2 (1,0)->3
    int s0  = dyp ? 3 : 0;               // even-x pixels (lo lanes)
    int s1  = dyp ? 1 : 2;               // odd-x pixels (hi lanes)
    int sb0 = s0 * 2 + b, sb1 = s1 * 2 + b;
    int off = h2 * 128 + xq * 2;
#pragma unroll
    for (int h = 0; h < 8; ++h) {
        float l01, h01, l23, h23;
        upk2f(qa01[h], l01, h01); upk2f(qa23[h], l23, h23);
        *(float2*)&g_Q[sb0][h][off] = make_float2(l01, l23);
        *(float2*)&g_Q[sb1][h][off] = make_float2(h01, h23);
        upk2f(ka01[h], l01, h01); upk2f(ka23[h], l23, h23);
        *(float2*)&g_K2[sb0][h][off] = make_float2(l01, l23);
        *(float2*)&g_K2[sb1][h][off] = make_float2(h01, h23);
        upk2f(va01[h], l01, h01); upk2f(va23[h], l23, h23);
        *(float2*)&g_V[sb0][h][off] = make_float2(l01, l23);
        *(float2*)&g_V[sb1][h][off] = make_float2(h01, h23);
    }
}

// ---------------------------------------------------------------------------
// K1T: tiled 128x128 plane transpose for Q, K2, V.
// ---------------------------------------------------------------------------
__global__ __launch_bounds__(256) void k_transpose()
{
    __shared__ float tile[32][33];
    int plane = blockIdx.y;
    const float* src;
    float* dst;
    if (blockIdx.z == 0)      { src = &g_Q [0][0][0]; dst = &g_QT [0][0][0]; }
    else if (blockIdx.z == 1) { src = &g_K2[0][0][0]; dst = &g_K2T[0][0][0]; }
    else                      { src = &g_V [0][0][0]; dst = &g_VT [0][0][0]; }
    src += (size_t)plane * PLANE;
    dst += (size_t)plane * PLANE;

    int tx = threadIdx.x, ty = threadIdx.y;
    int tilex = (blockIdx.x & 3) * 32;
    int tiley = (blockIdx.x >> 2) * 32;
#pragma unroll
    for (int k = 0; k < 4; ++k)
        tile[ty + k * 8][tx] = src[(tiley + ty + k * 8) * 128 + tilex + tx];
    __syncthreads();
#pragma unroll
    for (int k = 0; k < 4; ++k)
        dst[(tilex + ty + k * 8) * 128 + tiley + tx] = tile[tx][ty + k * 8];
}

// ---------------------------------------------------------------------------
// K2: axial attention, dual-pipe exp.
//  MSTEP: 2 keys via MUFU.EX2               (fma-pipe: 3, mufu: 2)
//  FSTEP: 2 keys via FFMA2 magic-round+deg3 (fma-pipe: 8, alu: 2 IMAD)
//  Per 16 keys: 5 MSTEP + 3 FSTEP pairs -> both pipes ~balanced.
//  K/V staged via LDS.128 (broadcast), halving shared-load issues.
// ---------------------------------------------------------------------------
#define EXP_MAGIC 12582912.0f  // 1.5 * 2^23

#define MSTEP(K2, V2)                                        \
    {                                                        \
        u64 s2 = mul2(q2, (K2));                             \
        float sl, sh; upk2f(s2, sl, sh);                     \
        u64 e2 = pk2f(ex2a(sl), ex2a(sh));                   \
        den_m = add2(den_m, e2);                             \
        num_m = fma2(e2, (V2), num_m);                       \
    }

#define FSTEP(K2, V2)                                        \
    {                                                        \
        u64 z2 = fma2(q2, (K2), MAGIC2);                     \
        u64 mc2 = fma2(z2, NEG1_2, MAGIC2);                  \
        u64 r2 = fma2(q2, (K2), mc2);                        \
        u64 p2 = fma2(C3_2, r2, C2_2);                       \
        p2 = fma2(p2, r2, C1_2);                             \
        p2 = fma2(p2, r2, C0_2);                             \
        u32 zl, zh, pl, ph;                                  \
        upk2u(z2, zl, zh);                                   \
        upk2u(p2, pl, ph);                                   \
        u64 e2 = pk2u(pl + zl * 8388608u, ph + zh * 8388608u); \
        den_f = add2(den_f, e2);                             \
        num_f = fma2(e2, (V2), num_f);                       \
    }

__global__ __launch_bounds__(256) void k_attn(
    const float* __restrict__ Wver, const float* __restrict__ Whor)
{
    __shared__ __align__(16) float s[3][8][256];
    __shared__ float swd[8];

    int t   = threadIdx.x;
    int bid = blockIdx.x;                 // 1024 = 2 dir * 8 sub * 64 groups
    int dir = bid >> 9;
    int sb  = (bid >> 6) & 7;
    int grp = bid & 63;
    int base = grp * 256;

    const float* qp = dir ? &g_QT [sb][0][0] : &g_Q [sb][0][0];
    const float* kp = dir ? &g_K2T[sb][0][0] : &g_K2[sb][0][0];
    const float* vp = dir ? &g_VT [sb][0][0] : &g_V [sb][0][0];

    for (int i = t; i < 2048; i += 256) {
        int head = i >> 8, off = i & 255;
        s[0][head][off] = qp[head * PLANE + base + off];
        s[1][head][off] = kp[head * PLANE + base + off];
        s[2][head][off] = vp[head * PLANE + base + off];
    }
    if (t < 8) swd[t] = dir ? Wver[t] : Whor[t];
    __syncthreads();

    const u64 MAGIC2 = pk2f(EXP_MAGIC, EXP_MAGIC);
    const u64 NEG1_2 = pk2f(-1.0f, -1.0f);
    // deg-3 Chebyshev fit of 2^r on [-0.5, 0.5], rel err ~1e-4
    const u64 C3_2 = pk2f(0.0559328f, 0.0559328f);
    const u64 C2_2 = pk2f(0.2426208f, 0.2426208f);
    const u64 C1_2 = pk2f(0.6931126f, 0.6931126f);
    const u64 C0_2 = pk2f(0.9999244f, 0.9999244f);

    int pos  = t & 127;
    int lsel = t >> 7;
    float facc = 0.f;

#pragma unroll 1
    for (int head = 0; head < 8; ++head) {
        float q = s[0][head][(lsel << 7) + pos];
        u64 q2 = pk2f(q, q);
        const ulonglong2* kk = (const ulonglong2*)&s[1][head][lsel << 7];
        const ulonglong2* vv = (const ulonglong2*)&s[2][head][lsel << 7];
        u64 den_m = 0ull, num_m = 0ull;   // packed (+0,+0)
        u64 den_f = 0ull, num_f = 0ull;
#pragma unroll 2
        for (int m = 0; m < 8; ++m) {     // 4x LDS.128 K + 4x LDS.128 V = 16 keys
            ulonglong2 k0 = kk[m * 4 + 0], k1 = kk[m * 4 + 1];
            ulonglong2 k2 = kk[m * 4 + 2], k3 = kk[m * 4 + 3];
            ulonglong2 v0 = vv[m * 4 + 0], v1 = vv[m * 4 + 1];
            ulonglong2 v2 = vv[m * 4 + 2], v3 = vv[m * 4 + 3];
            MSTEP(k0.x, v0.x)
            MSTEP(k0.y, v0.y)
            MSTEP(k1.x, v1.x)
            MSTEP(k1.y, v1.y)
            MSTEP(k2.x, v2.x)
            FSTEP(k2.y, v2.y)
            FSTEP(k3.x, v3.x)
            FSTEP(k3.y, v3.y)
        }
        u64 den2 = add2(den_m, den_f);
        u64 num2 = add2(num_m, num_f);
        float dl, dh, nl, nh;
        upk2f(den2, dl, dh);
        upk2f(num2, nl, nh);
        facc = fmaf(swd[head], __fdividef(nl + nh, dl + dh), facc);
    }
    g_flow[dir][sb][base + t] = facc;
}

// ---------------------------------------------------------------------------
// K3: bilinear border grid-sample + parity re-interleave.
// 4x channel-split; gathers batched 4 channels at a time (16 loads in flight).
// ---------------------------------------------------------------------------
__global__ __launch_bounds__(256) void k_warp(
    const float* __restrict__ ref, float* __restrict__ out)
{
    int idx = blockIdx.x * 256 + threadIdx.x;   // 524288
    int pix = idx & 16383;
    int cid = (idx >> 14) & 3;                  // channel chunk 0..3
    int sb  = idx >> 16;                        // 0..7
    int h2  = pix >> 7, w2 = pix & 127;
    int s   = sb >> 1, b = sb & 1;
    int dy  = (s == 1 || s == 3) ? 1 : 0;
    int dx  = (s == 1 || s == 2) ? 1 : 0;

    float fx = g_flow[0][sb][(h2 << 7) + w2];
    float fy = g_flow[1][sb][(w2 << 7) + h2];
    float ix = (float)w2 + fx;
    float iy = (float)h2 + fy;
    float x0f = floorf(ix), y0f = floorf(iy);
    float wx = ix - x0f, wy = iy - y0f;
    int x0 = (int)x0f, y0 = (int)y0f;
    int x0c = min(max(x0, 0), 127), x1c = min(max(x0 + 1, 0), 127);
    int y0c = min(max(y0, 0), 127), y1c = min(max(y0 + 1, 0), 127);

    int X0 = 2 * x0c + dx, X1 = 2 * x1c + dx;
    int Y0 = 2 * y0c + dy, Y1 = 2 * y1c + dy;
    int o00 = Y0 * 256 + X0, o01 = Y0 * 256 + X1;
    int o10 = Y1 * 256 + X0, o11 = Y1 * 256 + X1;

    float w11 = wx * wy;
    float w01 = wx - w11;
    float w10 = wy - w11;
    float w00 = 1.f - wx - wy + w11;

    int c0 = cid * 16;
    const float* rp = ref + ((size_t)b * 64 + c0) * 65536;
    float*       op = out + ((size_t)b * 64 + c0) * 65536
                          + (2 * h2 + dy) * 256 + (2 * w2 + dx);

#pragma unroll
    for (int cc = 0; cc < 16; cc += 4) {
        float t00[4], t01[4], t10[4], t11[4];
#pragma unroll
        for (int c = 0; c < 4; ++c) {
            const float* p = rp + (size_t)(cc + c) * 65536;
            t00[c] = p[o00];
            t01[c] = p[o01];
            t10[c] = p[o10];
            t11[c] = p[o11];
        }
#pragma unroll
        for (int c = 0; c < 4; ++c) {
            float v = w00 * t00[c];
            v = fmaf(w01, t01[c], v);
            v = fmaf(w10, t10[c], v);
            v = fmaf(w11, t11[c], v);
            op[(size_t)(cc + c) * 65536] = v;
        }
    }
}

// ---------------------------------------------------------------------------
extern "C" void kernel_launch(void* const* d_in, const int* in_sizes, int n_in,
                              void* d_out, int out_size)
{
    const float* cur  = (const float*)d_in[0];
    const float* ref  = (const float*)d_in[1];
    const float* Wq   = (const float*)d_in[2];
    const float* Wk   = (const float*)d_in[3];
    const float* Wv   = (const float*)d_in[4];
    const float* Wver = (const float*)d_in[5];
    const float* Whor = (const float*)d_in[6];
    float* out = (float*)d_out;

    k_qkv<<<128, 256>>>(cur, ref, Wq, Wk, Wv);
    k_transpose<<<dim3(16, 64, 3), dim3(32, 8)>>>();
    k_attn<<<1024, 256>>>(Wver, Whor);
    k_warp<<<2048, 256>>>(ref, out);
}

// round 4
// speedup vs baseline: 1.6455x; 1.6455x over previous
#include <cuda_runtime.h>
#include <cstdint>

// ---------------------------------------------------------------------------
// CrossWarpingModule: B=2, C=64, H=W=256 -> 4 parity sub-images of 128x128,
// 8-head axial attention (per-head channel dim = 1), flow, bilinear warp.
//
//   K1  k_qkv       : 1x1 convs -> Q, K, V  (raw K now; no log2e folding)
//   K1T k_transpose : transposed copies for the vertical axial pass
//   K2  k_attn      : MOMENT-BASED axial softmax. Scores are rank-1 (s=q*k),
//                     so exp(q*k) = sum_n q^n/n! * k^n and the attention
//                     reduces to 29 per-line moments + a deg-14 Horner per
//                     query. O(L*14) instead of O(L^2) exponentials.
//   K3  k_warp      : bilinear border grid-sample + parity re-interleave.
// ---------------------------------------------------------------------------

#define PLANE 16384  // 128*128
typedef unsigned long long u64;
typedef unsigned int u32;

__device__ float g_Q  [8][8][PLANE];
__device__ float g_K2 [8][8][PLANE];   // holds raw K
__device__ float g_V  [8][8][PLANE];
__device__ float g_QT [8][8][PLANE];
__device__ float g_K2T[8][8][PLANE];
__device__ float g_VT [8][8][PLANE];
__device__ float g_flow[2][8][PLANE];  // dir0 = horizontal, dir1 = vertical

// ------------------------- packed f32x2 helpers (k_qkv) --------------------
__device__ __forceinline__ u64 pk2f(float lo, float hi) {
    u64 r; asm("mov.b64 %0,{%1,%2};" : "=l"(r) : "f"(lo), "f"(hi)); return r;
}
__device__ __forceinline__ void upk2f(u64 v, float& lo, float& hi) {
    asm("mov.b64 {%0,%1},%2;" : "=f"(lo), "=f"(hi) : "l"(v));
}
__device__ __forceinline__ u64 fma2(u64 a, u64 b, u64 c) {
    u64 d; asm("fma.rn.f32x2 %0,%1,%2,%3;" : "=l"(d) : "l"(a), "l"(b), "l"(c)); return d;
}

// ---------------------------------------------------------------------------
// K1: QKV projections. One thread handles 4 consecutive original-x pixels.
// ---------------------------------------------------------------------------
__global__ __launch_bounds__(256) void k_qkv(
    const float* __restrict__ cur, const float* __restrict__ ref,
    const float* __restrict__ Wq, const float* __restrict__ Wk,
    const float* __restrict__ Wv)
{
    __shared__ u64 sW[3][512];
    int t = threadIdx.x;
    for (int i = t; i < 512; i += 256) {
        float wq = Wq[i];
        float wk = Wk[i];
        float wv = Wv[i];
        sW[0][i] = pk2f(wq, wq);
        sW[1][i] = pk2f(wk, wk);
        sW[2][i] = pk2f(wv, wv);
    }
    __syncthreads();

    int idx = blockIdx.x * 256 + t;      // 32768 = 2(b) * 256(y) * 64(xq)
    int b   = idx >> 14;
    int rem = idx & 16383;
    int y   = rem >> 6;
    int xq  = rem & 63;
    int h2  = y >> 1, dyp = y & 1;

    u64 qa01[8], qa23[8], ka01[8], ka23[8], va01[8], va23[8];
#pragma unroll
    for (int h = 0; h < 8; ++h) {
        qa01[h] = qa23[h] = 0ull;
        ka01[h] = ka23[h] = 0ull;
        va01[h] = va23[h] = 0ull;
    }

    const float* curp = cur + ((size_t)b * 64) * 65536 + y * 256 + xq * 4;
    const float* refp = ref + ((size_t)b * 64) * 65536 + y * 256 + xq * 4;

#pragma unroll 4
    for (int c = 0; c < 64; ++c) {
        float4 cv = *(const float4*)(curp + (size_t)c * 65536);
        float4 rv = *(const float4*)(refp + (size_t)c * 65536);
        u64 c01 = pk2f(cv.x, cv.y), c23 = pk2f(cv.z, cv.w);
        u64 r01 = pk2f(rv.x, rv.y), r23 = pk2f(rv.z, rv.w);
#pragma unroll
        for (int h = 0; h < 8; ++h) {
            u64 wq = sW[0][h * 64 + c];
            u64 wk = sW[1][h * 64 + c];
            u64 wv = sW[2][h * 64 + c];
            qa01[h] = fma2(wq, c01, qa01[h]);
            qa23[h] = fma2(wq, c23, qa23[h]);
            ka01[h] = fma2(wk, r01, ka01[h]);
            ka23[h] = fma2(wk, r23, ka23[h]);
            va01[h] = fma2(wv, r01, va01[h]);
            va23[h] = fma2(wv, r23, va23[h]);
        }
    }

    // parity sub mapping: (dy,dx) -> s : (0,0)->0 (1,1)->1 (0,1)->2 (1,0)->3
    int s0  = dyp ? 3 : 0;               // even-x pixels (lo lanes)
    int s1  = dyp ? 1 : 2;               // odd-x pixels (hi lanes)
    int sb0 = s0 * 2 + b, sb1 = s1 * 2 + b;
    int off = h2 * 128 + xq * 2;
#pragma unroll
    for (int h = 0; h < 8; ++h) {
        float l01, h01, l23, h23;
        upk2f(qa01[h], l01, h01); upk2f(qa23[h], l23, h23);
        *(float2*)&g_Q[sb0][h][off] = make_float2(l01, l23);
        *(float2*)&g_Q[sb1][h][off] = make_float2(h01, h23);
        upk2f(ka01[h], l01, h01); upk2f(ka23[h], l23, h23);
        *(float2*)&g_K2[sb0][h][off] = make_float2(l01, l23);
        *(float2*)&g_K2[sb1][h][off] = make_float2(h01, h23);
        upk2f(va01[h], l01, h01); upk2f(va23[h], l23, h23);
        *(float2*)&g_V[sb0][h][off] = make_float2(l01, l23);
        *(float2*)&g_V[sb1][h][off] = make_float2(h01, h23);
    }
}

// ---------------------------------------------------------------------------
// K1T: tiled 128x128 plane transpose for Q, K, V.
// ---------------------------------------------------------------------------
__global__ __launch_bounds__(256) void k_transpose()
{
    __shared__ float tile[32][33];
    int plane = blockIdx.y;
    const float* src;
    float* dst;
    if (blockIdx.z == 0)      { src = &g_Q [0][0][0]; dst = &g_QT [0][0][0]; }
    else if (blockIdx.z == 1) { src = &g_K2[0][0][0]; dst = &g_K2T[0][0][0]; }
    else                      { src = &g_V [0][0][0]; dst = &g_VT [0][0][0]; }
    src += (size_t)plane * PLANE;
    dst += (size_t)plane * PLANE;

    int tx = threadIdx.x, ty = threadIdx.y;
    int tilex = (blockIdx.x & 3) * 32;
    int tiley = (blockIdx.x >> 2) * 32;
#pragma unroll
    for (int k = 0; k < 4; ++k)
        tile[ty + k * 8][tx] = src[(tiley + ty + k * 8) * 128 + tilex + tx];
    __syncthreads();
#pragma unroll
    for (int k = 0; k < 4; ++k)
        dst[(tilex + ty + k * 8) * 128 + tiley + tx] = tile[tx][ty + k * 8];
}

// ---------------------------------------------------------------------------
// K2: moment-based axial attention.
// Warp per line. Each thread owns 4 positions (fully coalesced float4 LDG).
// Per head: build per-line Taylor moments M_n = sum k^n (n=1..14) and
// MV_n = sum k^n v (n=0..14), butterfly-reduce across the warp, then evaluate
//   den(q) = sum_n M_n q^n / n!,  num(q) = sum_n MV_n q^n / n!
// per query position via Horner; flow += w_head * num/den.
// ---------------------------------------------------------------------------
#define NDEG 14

__global__ __launch_bounds__(128) void k_attn(
    const float* __restrict__ Wver, const float* __restrict__ Whor)
{
    int wid  = threadIdx.x >> 5;
    int lane = threadIdx.x & 31;
    int bid  = blockIdx.x;               // 512 = 2 dir * 8 sb * 32 groups
    int dir  = bid >> 8;
    int sb   = (bid >> 5) & 7;
    int lg   = bid & 31;
    int line = lg * 4 + wid;

    const float* qp = dir ? &g_QT [sb][0][0] : &g_Q [sb][0][0];
    const float* kp = dir ? &g_K2T[sb][0][0] : &g_K2[sb][0][0];
    const float* vp = dir ? &g_VT [sb][0][0] : &g_V [sb][0][0];
    const float* wdp = dir ? Wver : Whor;

    int base = line * 128 + lane * 4;

    const float invf[NDEG + 1] = {
        1.0f, 1.0f, 0.5f, 1.0f / 6.0f, 1.0f / 24.0f, 1.0f / 120.0f,
        1.0f / 720.0f, 1.0f / 5040.0f, 1.0f / 40320.0f, 1.0f / 362880.0f,
        1.0f / 3628800.0f, 1.0f / 39916800.0f, 1.0f / 479001600.0f,
        1.0f / 6227020800.0f, 1.0f / 87178291200.0f };

    float fl0 = 0.f, fl1 = 0.f, fl2 = 0.f, fl3 = 0.f;

    float4 q4 = *(const float4*)(qp + base);
    float4 k4 = *(const float4*)(kp + base);
    float4 v4 = *(const float4*)(vp + base);

#pragma unroll 1
    for (int head = 0; head < 8; ++head) {
        // prefetch next head
        float4 nq, nk, nv;
        if (head < 7) {
            nq = *(const float4*)(qp + (head + 1) * PLANE + base);
            nk = *(const float4*)(kp + (head + 1) * PLANE + base);
            nv = *(const float4*)(vp + (head + 1) * PLANE + base);
        }
        float wdh = wdp[head];

        float m[NDEG + 1];
        float mv[NDEG + 1];
#pragma unroll
        for (int n = 0; n <= NDEG; ++n) { m[n] = 0.f; mv[n] = 0.f; }

        // local moment contributions (4 positions)
        {
            float kk, vv, tt;
#define ACCUM(KX, VX)                                        \
            kk = (KX); vv = (VX); tt = kk;                   \
            mv[0] += vv;                                     \
            _Pragma("unroll")                                \
            for (int n = 1; n <= NDEG; ++n) {                \
                m[n] += tt;                                  \
                mv[n] = fmaf(tt, vv, mv[n]);                 \
                tt *= kk;                                    \
            }
            ACCUM(k4.x, v4.x)
            ACCUM(k4.y, v4.y)
            ACCUM(k4.z, v4.z)
            ACCUM(k4.w, v4.w)
#undef ACCUM
        }

        // butterfly reduction across the warp (29 live scalars)
#pragma unroll
        for (int off = 16; off; off >>= 1) {
            mv[0] += __shfl_xor_sync(0xffffffffu, mv[0], off);
#pragma unroll
            for (int n = 1; n <= NDEG; ++n) {
                m[n]  += __shfl_xor_sync(0xffffffffu, m[n],  off);
                mv[n] += __shfl_xor_sync(0xffffffffu, mv[n], off);
            }
        }

        // fold 1/n! into the moments (a_n = M_n/n!, b_n = MV_n/n!)
        m[0] = 128.0f;
#pragma unroll
        for (int n = 2; n <= NDEG; ++n) {
            m[n]  *= invf[n];
            mv[n] *= invf[n];
        }

        // Horner evaluation per query position
#define EVAL(QX, FL)                                          \
        {                                                     \
            float q = (QX);                                   \
            float den = m[NDEG], num = mv[NDEG];              \
            _Pragma("unroll")                                 \
            for (int n = NDEG - 1; n >= 0; --n) {             \
                den = fmaf(den, q, m[n]);                     \
                num = fmaf(num, q, mv[n]);                    \
            }                                                 \
            FL = fmaf(wdh, __fdividef(num, den), FL);         \
        }
        EVAL(q4.x, fl0)
        EVAL(q4.y, fl1)
        EVAL(q4.z, fl2)
        EVAL(q4.w, fl3)
#undef EVAL

        q4 = nq; k4 = nk; v4 = nv;
    }

    *(float4*)&g_flow[dir][sb][base] = make_float4(fl0, fl1, fl2, fl3);
}

// ---------------------------------------------------------------------------
// K3: bilinear border grid-sample + parity re-interleave.
// 4x channel-split; gathers batched 4 channels at a time.
// ---------------------------------------------------------------------------
__global__ __launch_bounds__(256) void k_warp(
    const float* __restrict__ ref, float* __restrict__ out)
{
    int idx = blockIdx.x * 256 + threadIdx.x;   // 524288
    int pix = idx & 16383;
    int cid = (idx >> 14) & 3;                  // channel chunk 0..3
    int sb  = idx >> 16;                        // 0..7
    int h2  = pix >> 7, w2 = pix & 127;
    int s   = sb >> 1, b = sb & 1;
    int dy  = (s == 1 || s == 3) ? 1 : 0;
    int dx  = (s == 1 || s == 2) ? 1 : 0;

    float fx = g_flow[0][sb][(h2 << 7) + w2];
    float fy = g_flow[1][sb][(w2 << 7) + h2];
    float ix = (float)w2 + fx;
    float iy = (float)h2 + fy;
    float x0f = floorf(ix), y0f = floorf(iy);
    float wx = ix - x0f, wy = iy - y0f;
    int x0 = (int)x0f, y0 = (int)y0f;
    int x0c = min(max(x0, 0), 127), x1c = min(max(x0 + 1, 0), 127);
    int y0c = min(max(y0, 0), 127), y1c = min(max(y0 + 1, 0), 127);

    int X0 = 2 * x0c + dx, X1 = 2 * x1c + dx;
    int Y0 = 2 * y0c + dy, Y1 = 2 * y1c + dy;
    int o00 = Y0 * 256 + X0, o01 = Y0 * 256 + X1;
    int o10 = Y1 * 256 + X0, o11 = Y1 * 256 + X1;

    float w11 = wx * wy;
    float w01 = wx - w11;
    float w10 = wy - w11;
    float w00 = 1.f - wx - wy + w11;

    int c0 = cid * 16;
    const float* rp = ref + ((size_t)b * 64 + c0) * 65536;
    float*       op = out + ((size_t)b * 64 + c0) * 65536
                          + (2 * h2 + dy) * 256 + (2 * w2 + dx);

#pragma unroll
    for (int cc = 0; cc < 16; cc += 4) {
        float t00[4], t01[4], t10[4], t11[4];
#pragma unroll
        for (int c = 0; c < 4; ++c) {
            const float* p = rp + (size_t)(cc + c) * 65536;
            t00[c] = p[o00];
            t01[c] = p[o01];
            t10[c] = p[o10];
            t11[c] = p[o11];
        }
#pragma unroll
        for (int c = 0; c < 4; ++c) {
            float v = w00 * t00[c];
            v = fmaf(w01, t01[c], v);
            v = fmaf(w10, t10[c], v);
            v = fmaf(w11, t11[c], v);
            op[(size_t)(cc + c) * 65536] = v;
        }
    }
}

// ---------------------------------------------------------------------------
extern "C" void kernel_launch(void* const* d_in, const int* in_sizes, int n_in,
                              void* d_out, int out_size)
{
    const float* cur  = (const float*)d_in[0];
    const float* ref  = (const float*)d_in[1];
    const float* Wq   = (const float*)d_in[2];
    const float* Wk   = (const float*)d_in[3];
    const float* Wv   = (const float*)d_in[4];
    const float* Wver = (const float*)d_in[5];
    const float* Whor = (const float*)d_in[6];
    float* out = (float*)d_out;

    k_qkv<<<128, 256>>>(cur, ref, Wq, Wk, Wv);
    k_transpose<<<dim3(16, 64, 3), dim3(32, 8)>>>();
    k_attn<<<512, 128>>>(Wver, Whor);
    k_warp<<<2048, 256>>>(ref, out);
}

// round 5
// speedup vs baseline: 1.7839x; 1.0842x over previous
#include <cuda_runtime.h>
#include <cstdint>

// ---------------------------------------------------------------------------
// CrossWarpingModule: B=2, C=64, H=W=256 -> 4 parity sub-images of 128x128,
// 8-head axial attention (per-head channel dim = 1), flow, bilinear warp.
//
//   K1  k_qkv  : 1x1 convs -> Q, K, V (thread-per-2-pixels, high occupancy)
//   K2  k_attn : MOMENT-BASED axial softmax. exp(q*k) = sum_n q^n/n! k^n, so
//                attention needs only 29 per-line moments + deg-14 Horner per
//                query. Vertical direction transposes in-kernel via smem
//                (no separate transpose kernel, no QT/KT/VT arrays).
//   K3  k_warp : bilinear border grid-sample + parity re-interleave.
// ---------------------------------------------------------------------------

#define PLANE 16384  // 128*128
typedef unsigned long long u64;
typedef unsigned int u32;

__device__ float g_Q [8][8][PLANE];
__device__ float g_K [8][8][PLANE];
__device__ float g_V [8][8][PLANE];
__device__ float g_flow[2][8][PLANE];  // dir0 = horizontal, dir1 = vertical

// ------------------------- packed f32x2 helpers ----------------------------
__device__ __forceinline__ u64 pk2f(float lo, float hi) {
    u64 r; asm("mov.b64 %0,{%1,%2};" : "=l"(r) : "f"(lo), "f"(hi)); return r;
}
__device__ __forceinline__ void upk2f(u64 v, float& lo, float& hi) {
    asm("mov.b64 {%0,%1},%2;" : "=f"(lo), "=f"(hi) : "l"(v));
}
__device__ __forceinline__ u64 fma2(u64 a, u64 b, u64 c) {
    u64 d; asm("fma.rn.f32x2 %0,%1,%2,%3;" : "=l"(d) : "l"(a), "l"(b), "l"(c)); return d;
}

// ---------------------------------------------------------------------------
// K1: QKV projections. Thread per 2 consecutive original-x pixels (one even,
// one odd -> the two x-parity sub-images), packed into one f32x2 lane pair.
// 256 blocks x 256 threads for full-chip streaming occupancy.
// ---------------------------------------------------------------------------
__global__ __launch_bounds__(256) void k_qkv(
    const float* __restrict__ cur, const float* __restrict__ ref,
    const float* __restrict__ Wq, const float* __restrict__ Wk,
    const float* __restrict__ Wv)
{
    __shared__ u64 sW[3][512];
    int t = threadIdx.x;
    for (int i = t; i < 512; i += 256) {
        float wq = Wq[i];
        float wk = Wk[i];
        float wv = Wv[i];
        sW[0][i] = pk2f(wq, wq);
        sW[1][i] = pk2f(wk, wk);
        sW[2][i] = pk2f(wv, wv);
    }
    __syncthreads();

    int idx = blockIdx.x * 256 + t;      // 65536 = 2(b) * 256(y) * 128(xpair)
    int b   = idx >> 15;
    int rem = idx & 32767;
    int y   = rem >> 7;
    int xq  = rem & 127;
    int h2  = y >> 1, dyp = y & 1;

    u64 qa[8], ka[8], va[8];
#pragma unroll
    for (int h = 0; h < 8; ++h) { qa[h] = 0ull; ka[h] = 0ull; va[h] = 0ull; }

    const float* curp = cur + ((size_t)b * 64) * 65536 + y * 256 + xq * 2;
    const float* refp = ref + ((size_t)b * 64) * 65536 + y * 256 + xq * 2;

#pragma unroll 4
    for (int c = 0; c < 64; ++c) {
        float2 cv = *(const float2*)(curp + (size_t)c * 65536);
        float2 rv = *(const float2*)(refp + (size_t)c * 65536);
        u64 c01 = pk2f(cv.x, cv.y);
        u64 r01 = pk2f(rv.x, rv.y);
#pragma unroll
        for (int h = 0; h < 8; ++h) {
            qa[h] = fma2(sW[0][h * 64 + c], c01, qa[h]);
            ka[h] = fma2(sW[1][h * 64 + c], r01, ka[h]);
            va[h] = fma2(sW[2][h * 64 + c], r01, va[h]);
        }
    }

    // parity sub mapping: (dy,dx) -> s : (0,0)->0 (1,1)->1 (0,1)->2 (1,0)->3
    int s0  = dyp ? 3 : 0;               // even-x pixel (lo lane)
    int s1  = dyp ? 1 : 2;               // odd-x pixel (hi lane)
    int sb0 = s0 * 2 + b, sb1 = s1 * 2 + b;
    int off = h2 * 128 + xq;
#pragma unroll
    for (int h = 0; h < 8; ++h) {
        float lo, hi;
        upk2f(qa[h], lo, hi);
        g_Q[sb0][h][off] = lo; g_Q[sb1][h][off] = hi;
        upk2f(ka[h], lo, hi);
        g_K[sb0][h][off] = lo; g_K[sb1][h][off] = hi;
        upk2f(va[h], lo, hi);
        g_V[sb0][h][off] = lo; g_V[sb1][h][off] = hi;
    }
}

// ---------------------------------------------------------------------------
// K2: moment-based axial attention with in-kernel transpose for dir=1.
// Block = (dir, sb, 4 lines); 128 threads, warp per line.
// Stage Q/K/V for all 8 heads of the block's 4 lines into smem:
//   dir=0: coalesced float4 row loads.
//   dir=1: row-strided float4 loads (rows = positions, 4 target columns),
//          scattered transposed into smem.
// Then per head: per-line Taylor moments M_n = sum k^n, MV_n = sum k^n v
// (n<=14), butterfly-reduced across the warp, and per-query Horner:
//   flow += w_head * (sum MV_n q^n/n!) / (sum M_n q^n/n!)
// ---------------------------------------------------------------------------
#define NDEG 14

__global__ __launch_bounds__(128) void k_attn(
    const float* __restrict__ Wver, const float* __restrict__ Whor)
{
    __shared__ float sT[3][8][4][128];   // arr, head, line-in-block, pos (48KB)

    int t    = threadIdx.x;
    int wid  = t >> 5;
    int lane = t & 31;
    int bid  = blockIdx.x;               // 512 = 2 dir * 8 sb * 32 groups
    int dir  = bid >> 8;
    int sb   = (bid >> 5) & 7;
    int lg   = bid & 31;
    int c0   = lg * 4;                   // first line of this block

    const float* base_arr[3] = { &g_Q[sb][0][0], &g_K[sb][0][0], &g_V[sb][0][0] };

    // ---- stage into smem ----
    if (dir == 0) {
        // thread t loads line (c0 + wid), positions lane*4..+3 per (arr, head)
        int off = (c0 + wid) * 128 + lane * 4;
#pragma unroll
        for (int a = 0; a < 3; ++a)
#pragma unroll
            for (int h = 0; h < 8; ++h) {
                float4 v = *(const float4*)(base_arr[a] + h * PLANE + off);
                *(float4*)&sT[a][h][wid][lane * 4] = v;
            }
    } else {
        // vertical: lines are columns c0..c0+3; thread t loads row t's float4
        int off = t * 128 + c0;
#pragma unroll
        for (int a = 0; a < 3; ++a)
#pragma unroll
            for (int h = 0; h < 8; ++h) {
                float4 v = *(const float4*)(base_arr[a] + h * PLANE + off);
                sT[a][h][0][t] = v.x;
                sT[a][h][1][t] = v.y;
                sT[a][h][2][t] = v.z;
                sT[a][h][3][t] = v.w;
            }
    }
    __syncthreads();

    const float* wdp = dir ? Wver : Whor;

    const float invf[NDEG + 1] = {
        1.0f, 1.0f, 0.5f, 1.0f / 6.0f, 1.0f / 24.0f, 1.0f / 120.0f,
        1.0f / 720.0f, 1.0f / 5040.0f, 1.0f / 40320.0f, 1.0f / 362880.0f,
        1.0f / 3628800.0f, 1.0f / 39916800.0f, 1.0f / 479001600.0f,
        1.0f / 6227020800.0f, 1.0f / 87178291200.0f };

    float fl0 = 0.f, fl1 = 0.f, fl2 = 0.f, fl3 = 0.f;

#pragma unroll 1
    for (int head = 0; head < 8; ++head) {
        float wdh = wdp[head];
        float4 q4 = *(const float4*)&sT[0][head][wid][lane * 4];
        float4 k4 = *(const float4*)&sT[1][head][wid][lane * 4];
        float4 v4 = *(const float4*)&sT[2][head][wid][lane * 4];

        float m[NDEG + 1];
        float mv[NDEG + 1];
#pragma unroll
        for (int n = 0; n <= NDEG; ++n) { m[n] = 0.f; mv[n] = 0.f; }

        // local moment contributions (4 positions)
        {
            float kk, vv, tt;
#define ACCUM(KX, VX)                                        \
            kk = (KX); vv = (VX); tt = kk;                   \
            mv[0] += vv;                                     \
            _Pragma("unroll")                                \
            for (int n = 1; n <= NDEG; ++n) {                \
                m[n] += tt;                                  \
                mv[n] = fmaf(tt, vv, mv[n]);                 \
                tt *= kk;                                    \
            }
            ACCUM(k4.x, v4.x)
            ACCUM(k4.y, v4.y)
            ACCUM(k4.z, v4.z)
            ACCUM(k4.w, v4.w)
#undef ACCUM
        }

        // butterfly reduction across the warp (29 live scalars)
#pragma unroll
        for (int off = 16; off; off >>= 1) {
            mv[0] += __shfl_xor_sync(0xffffffffu, mv[0], off);
#pragma unroll
            for (int n = 1; n <= NDEG; ++n) {
                m[n]  += __shfl_xor_sync(0xffffffffu, m[n],  off);
                mv[n] += __shfl_xor_sync(0xffffffffu, mv[n], off);
            }
        }

        // fold 1/n! into the moments
        m[0] = 128.0f;
#pragma unroll
        for (int n = 2; n <= NDEG; ++n) {
            m[n]  *= invf[n];
            mv[n] *= invf[n];
        }

        // Horner evaluation per query position
#define EVAL(QX, FL)                                          \
        {                                                     \
            float q = (QX);                                   \
            float den = m[NDEG], num = mv[NDEG];              \
            _Pragma("unroll")                                 \
            for (int n = NDEG - 1; n >= 0; --n) {             \
                den = fmaf(den, q, m[n]);                     \
                num = fmaf(num, q, mv[n]);                    \
            }                                                 \
            FL = fmaf(wdh, __fdividef(num, den), FL);         \
        }
        EVAL(q4.x, fl0)
        EVAL(q4.y, fl1)
        EVAL(q4.z, fl2)
        EVAL(q4.w, fl3)
#undef EVAL
    }

    int base = (c0 + wid) * 128 + lane * 4;
    *(float4*)&g_flow[dir][sb][base] = make_float4(fl0, fl1, fl2, fl3);
}

// ---------------------------------------------------------------------------
// K3: bilinear border grid-sample + parity re-interleave.
// 4x channel-split; gathers batched 4 channels at a time.
// ---------------------------------------------------------------------------
__global__ __launch_bounds__(256) void k_warp(
    const float* __restrict__ ref, float* __restrict__ out)
{
    int idx = blockIdx.x * 256 + threadIdx.x;   // 524288
    int pix = idx & 16383;
    int cid = (idx >> 14) & 3;                  // channel chunk 0..3
    int sb  = idx >> 16;                        // 0..7
    int h2  = pix >> 7, w2 = pix & 127;
    int s   = sb >> 1, b = sb & 1;
    int dy  = (s == 1 || s == 3) ? 1 : 0;
    int dx  = (s == 1 || s == 2) ? 1 : 0;

    float fx = g_flow[0][sb][(h2 << 7) + w2];
    float fy = g_flow[1][sb][(w2 << 7) + h2];
    float ix = (float)w2 + fx;
    float iy = (float)h2 + fy;
    float x0f = floorf(ix), y0f = floorf(iy);
    float wx = ix - x0f, wy = iy - y0f;
    int x0 = (int)x0f, y0 = (int)y0f;
    int x0c = min(max(x0, 0), 127), x1c = min(max(x0 + 1, 0), 127);
    int y0c = min(max(y0, 0), 127), y1c = min(max(y0 + 1, 0), 127);

    int X0 = 2 * x0c + dx, X1 = 2 * x1c + dx;
    int Y0 = 2 * y0c + dy, Y1 = 2 * y1c + dy;
    int o00 = Y0 * 256 + X0, o01 = Y0 * 256 + X1;
    int o10 = Y1 * 256 + X0, o11 = Y1 * 256 + X1;

    float w11 = wx * wy;
    float w01 = wx - w11;
    float w10 = wy - w11;
    float w00 = 1.f - wx - wy + w11;

    int c0 = cid * 16;
    const float* rp = ref + ((size_t)b * 64 + c0) * 65536;
    float*       op = out + ((size_t)b * 64 + c0) * 65536
                          + (2 * h2 + dy) * 256 + (2 * w2 + dx);

#pragma unroll
    for (int cc = 0; cc < 16; cc += 4) {
        float t00[4], t01[4], t10[4], t11[4];
#pragma unroll
        for (int c = 0; c < 4; ++c) {
            const float* p = rp + (size_t)(cc + c) * 65536;
            t00[c] = p[o00];
            t01[c] = p[o01];
            t10[c] = p[o10];
            t11[c] = p[o11];
        }
#pragma unroll
        for (int c = 0; c < 4; ++c) {
            float v = w00 * t00[c];
            v = fmaf(w01, t01[c], v);
            v = fmaf(w10, t10[c], v);
            v = fmaf(w11, t11[c], v);
            op[(size_t)(cc + c) * 65536] = v;
        }
    }
}

// ---------------------------------------------------------------------------
extern "C" void kernel_launch(void* const* d_in, const int* in_sizes, int n_in,
                              void* d_out, int out_size)
{
    const float* cur  = (const float*)d_in[0];
    const float* ref  = (const float*)d_in[1];
    const float* Wq   = (const float*)d_in[2];
    const float* Wk   = (const float*)d_in[3];
    const float* Wv   = (const float*)d_in[4];
    const float* Wver = (const float*)d_in[5];
    const float* Whor = (const float*)d_in[6];
    float* out = (float*)d_out;

    k_qkv<<<256, 256>>>(cur, ref, Wq, Wk, Wv);
    k_attn<<<512, 128>>>(Wver, Whor);
    k_warp<<<2048, 256>>>(ref, out);
}